// round 6
// baseline (speedup 1.0000x reference)
#include <cuda_runtime.h>

// DotProductCostVolume: out[b,d,h,w] = (1/C) * sum_c left[b,c,h,w]*right[b,c,h,w-d], 0 if w<d
// B=4, C=32, H=256, W=512, D=64, fp32.
//
// CTA = (b, h, 128-wide w-tile), 128 threads, 4 CTAs/SM. Stage L[32c x 128w] +
// R[32c x 192w] (halo zero-filled -> w<d masking automatic), 16B-chunk XOR
// swizzle. Per-thread 8w x 8d tile via packed fma.rn.f32x2.
// R6 changes vs R5:
//  - lane remap (warp = 4 wg x 8 dg): L LDS become 8-way broadcast (4 distinct
//    addrs/warp), R LDS collapse to 11 distinct diagonal addrs/warp -> shared
//    crossbar demand drops ~2x (was the top pipe at 79%).
//  - even-parity f32x2 operand pairs taken as free register-pair views of the
//    LDS.128 quads (union aliasing); only 7 odd pairs/channel still packed.

#define Bn 4
#define Cn 32
#define Hn 256
#define Wn 512
#define Dn 64
#define TW 128           // output w-columns per CTA
#define RW 192           // TW + 64 halo columns of right
#define NT 128           // threads per CTA

#define LCH (TW/4)       // 32 float4 chunks per L row
#define RCH (RW/4)       // 48 float4 chunks per R row

typedef unsigned long long ull;

union F4U { float4 f; ull u[2]; float s[4]; };

// 16B-chunk XOR swizzle (row-local chunk index q)
__device__ __forceinline__ int swc(int q) { return q ^ ((q >> 3) & 7); }

__device__ __forceinline__ ull pk(float lo, float hi) {
    ull r;
    asm("mov.b64 %0, {%1, %2};" : "=l"(r) : "f"(lo), "f"(hi));
    return r;
}
__device__ __forceinline__ void fma2(ull& d, ull a, ull b) {
    asm("fma.rn.f32x2 %0, %1, %2, %0;" : "+l"(d) : "l"(a), "l"(b));
}
__device__ __forceinline__ ull mul2(ull a, ull b) {
    ull r;
    asm("mul.rn.f32x2 %0, %1, %2;" : "=l"(r) : "l"(a), "l"(b));
    return r;
}
__device__ __forceinline__ void upk(ull v, float& lo, float& hi) {
    asm("mov.b64 {%0, %1}, %2;" : "=f"(lo), "=f"(hi) : "l"(v));
}

__global__ __launch_bounds__(NT, 4)
void cost_volume_kernel(const float* __restrict__ left,
                        const float* __restrict__ right,
                        float* __restrict__ out)
{
    __shared__ float4 Ls4[Cn * LCH];   // 16 KB
    __shared__ float4 Rs4[Cn * RCH];   // 24 KB

    const int tile = blockIdx.x;    // 0..3
    const int h    = blockIdx.y;    // 0..255
    const int b    = blockIdx.z;    // 0..3
    const int w0   = tile * TW;
    const int tid  = threadIdx.x;

    const float* lbase = left  + ((long)(b * Cn) * Hn + h) * Wn;
    const float* rbase = right + ((long)(b * Cn) * Hn + h) * Wn;

    // ---- Stage left tile ----
    #pragma unroll 4
    for (int t = tid; t < Cn * LCH; t += NT) {
        int c = t >> 5;             // / 32
        int q = t & (LCH - 1);
        float4 v = *reinterpret_cast<const float4*>(lbase + (long)c * Hn * Wn + w0 + 4 * q);
        Ls4[c * LCH + swc(q)] = v;
    }

    // ---- Stage right tile with halo (zero for w<0) ----
    #pragma unroll 4
    for (int t = tid; t < Cn * RCH; t += NT) {
        int c  = t / RCH;
        int q  = t - c * RCH;
        int gw = w0 - 64 + 4 * q;   // chunk entirely <0 or entirely >=0
        float4 v;
        if (gw >= 0)
            v = *reinterpret_cast<const float4*>(rbase + (long)c * Hn * Wn + gw);
        else
            v = make_float4(0.f, 0.f, 0.f, 0.f);
        Rs4[c * RCH + swc(q)] = v;
    }
    __syncthreads();

    // ---- Lane remap: warp covers 4 w-groups x 8 d-groups ----
    const int lane = tid & 31;
    const int wg = ((tid >> 5) << 2) | (lane >> 3);  // 0..15  w: w0+8wg..+7
    const int dg = lane & 7;                         // 0..7   d: 8dg..+7

    const float4* La = &Ls4[swc(2 * wg)];
    const float4* Lb = &Ls4[swc(2 * wg + 1)];

    // R words rv[n] = word (8wg - 8dg + 56) + n, n in [0,15]; base 4-aligned.
    const int q0 = 2 * (wg - dg) + 14;           // in [0, 44]
    const float4* R0 = &Rs4[swc(q0 + 0)];
    const float4* R1 = &Rs4[swc(q0 + 1)];
    const float4* R2 = &Rs4[swc(q0 + 2)];
    const float4* R3 = &Rs4[swc(q0 + 3)];

    // acc2[a][j] = ( acc[2a][j] , acc[2a+1][j] )
    ull acc2[4][8];
    #pragma unroll
    for (int a = 0; a < 4; a++)
        #pragma unroll
        for (int j = 0; j < 8; j++)
            acc2[a][j] = 0ull;

    #pragma unroll 8
    for (int c = 0; c < Cn; c++) {
        F4U la, lb, r0, r1, r2, r3;
        la.f = La[c * LCH];
        lb.f = Lb[c * LCH];
        r0.f = R0[c * RCH];
        r1.f = R1[c * RCH];
        r2.f = R2[c * RCH];
        r3.f = R3[c * RCH];

        // L pairs: free aligned views
        ull L2[4] = { la.u[0], la.u[1], lb.u[0], lb.u[1] };

        // Even R pairs E[t] = (rv[2t], rv[2t+1]): free aligned views
        ull E[8] = { r0.u[0], r0.u[1], r1.u[0], r1.u[1],
                     r2.u[0], r2.u[1], r3.u[0], r3.u[1] };

        // Odd R pairs O[s] = (rv[2s+1], rv[2s+2]), s=0..6: packed
        float rv[16] = { r0.s[0], r0.s[1], r0.s[2], r0.s[3],
                         r1.s[0], r1.s[1], r1.s[2], r1.s[3],
                         r2.s[0], r2.s[1], r2.s[2], r2.s[3],
                         r3.s[0], r3.s[1], r3.s[2], r3.s[3] };
        ull O[7];
        #pragma unroll
        for (int s = 0; s < 7; s++)
            O[s] = pk(rv[2 * s + 1], rv[2 * s + 2]);

        // acc[i][j] += l[i]*rv[8+i-j]; pair i=2a,2a+1 -> m = 8+2a-j in [1,14]
        #pragma unroll
        for (int a = 0; a < 4; a++)
            #pragma unroll
            for (int j = 0; j < 8; j++) {
                const int m = 8 + 2 * a - j;
                fma2(acc2[a][j], L2[a], (m & 1) ? O[(m - 1) >> 1] : E[m >> 1]);
            }
    }

    // ---- Epilogue: scale by 1/C (packed), unpack, vectorized stores ----
    const float sc = 1.0f / (float)Cn;
    const ull SC = pk(sc, sc);
    float* ob = out + ((long)(b * Dn) * Hn + h) * Wn + w0 + wg * 8;
    #pragma unroll
    for (int j = 0; j < 8; j++) {
        int d = dg * 8 + j;
        float a0, a1, a2, a3, a4, a5, a6, a7;
        upk(mul2(acc2[0][j], SC), a0, a1);
        upk(mul2(acc2[1][j], SC), a2, a3);
        upk(mul2(acc2[2][j], SC), a4, a5);
        upk(mul2(acc2[3][j], SC), a6, a7);
        float4* p = reinterpret_cast<float4*>(ob + (long)d * Hn * Wn);
        p[0] = make_float4(a0, a1, a2, a3);
        p[1] = make_float4(a4, a5, a6, a7);
    }
}

extern "C" void kernel_launch(void* const* d_in, const int* in_sizes, int n_in,
                              void* d_out, int out_size)
{
    const float* left  = (const float*)d_in[0];
    const float* right = (const float*)d_in[1];
    float* out = (float*)d_out;

    dim3 grid(Wn / TW, Hn, Bn);   // (4, 256, 4) = 4096 CTAs
    cost_volume_kernel<<<grid, NT>>>(left, right, out);
}

// round 7
// speedup vs baseline: 1.2424x; 1.2424x over previous
#include <cuda_runtime.h>
#include <cstdint>

// DotProductCostVolume: out[b,d,h,w] = (1/C) * sum_c left[b,c,h,w]*right[b,c,h,w-d], 0 if w<d
// B=4, C=32, H=256, W=512, D=64, fp32.
//
// CTA = (b, h, 128-wide w-tile), 128 threads, 4 CTAs/SM.
// R7: channel-chunked double-buffered cp.async pipeline (4 chunks x 8 channels):
// global loads of chunk cc+1 overlap FMAs on chunk cc, so DRAM traffic flows
// continuously instead of burst->idle->burst (R3-R6 were overlap-bound at
// ~2.2TB/s). Halo zero-filled via cp.async zfill -> w<d masking automatic.
// Streaming stores (__stcs) keep the 128MB output from evicting input reuse.

#define Bn 4
#define Cn 32
#define Hn 256
#define Wn 512
#define Dn 64
#define TW 128           // output w-columns per CTA
#define RW 192           // TW + 64 halo columns of right
#define NT 128           // threads per CTA
#define CH 8             // channels per pipeline chunk
#define NCH (Cn/CH)      // 4 chunks

#define LCH (TW/4)       // 32 float4 chunks per L row
#define RCH (RW/4)       // 48 float4 chunks per R row
#define LST (CH*LCH)     // 256 float4 per L stage
#define RST (CH*RCH)     // 384 float4 per R stage

// 16B-chunk XOR swizzle (row-local chunk index q): conflict-free LDS.128.
__device__ __forceinline__ int swc(int q) { return q ^ ((q >> 3) & 7); }

__device__ __forceinline__ void cp16(uint32_t s, const void* g, bool valid) {
    asm volatile("cp.async.cg.shared.global [%0], [%1], 16, %2;"
                 :: "r"(s), "l"(g), "r"(valid ? 16 : 0));
}
__device__ __forceinline__ void cp_commit() {
    asm volatile("cp.async.commit_group;");
}

__global__ __launch_bounds__(NT, 4)
void cost_volume_kernel(const float* __restrict__ left,
                        const float* __restrict__ right,
                        float* __restrict__ out)
{
    __shared__ float4 Ls4[2 * LST];   // 8 KB
    __shared__ float4 Rs4[2 * RST];   // 12 KB

    const int tile = blockIdx.x;    // 0..3
    const int h    = blockIdx.y;    // 0..255
    const int b    = blockIdx.z;    // 0..3
    const int w0   = tile * TW;
    const int tid  = threadIdx.x;

    const float* lbase = left  + ((long)(b * Cn) * Hn + h) * Wn;
    const float* rbase = right + ((long)(b * Cn) * Hn + h) * Wn;

    const uint32_t lsm = (uint32_t)__cvta_generic_to_shared(Ls4);
    const uint32_t rsm = (uint32_t)__cvta_generic_to_shared(Rs4);

    // Prefetch one 8-channel chunk into stage st.
    auto prefetch = [&](int cc, int st) {
        const int c0 = cc * CH;
        // L: 256 float4 per stage, 2 per thread
        #pragma unroll
        for (int it = 0; it < 2; it++) {
            int idx = tid + it * NT;
            int ch = idx >> 5;          // /32
            int q  = idx & (LCH - 1);
            cp16(lsm + (uint32_t)(st * LST + ch * LCH + swc(q)) * 16,
                 lbase + (long)(c0 + ch) * Hn * Wn + w0 + 4 * q, true);
        }
        // R: 384 float4 per stage, 3 per thread (halo: zfill for gw<0)
        #pragma unroll
        for (int it = 0; it < 3; it++) {
            int idx = tid + it * NT;
            int ch = idx / RCH;
            int q  = idx - ch * RCH;
            int gw = w0 - 64 + 4 * q;   // chunk entirely <0 or entirely >=0
            bool v = (gw >= 0);
            cp16(rsm + (uint32_t)(st * RST + ch * RCH + swc(q)) * 16,
                 rbase + (long)(c0 + ch) * Hn * Wn + (v ? gw : 0), v);
        }
        cp_commit();
    };

    // ---- Per-thread 8w x 8d register tile ----
    const int wg = tid & 15;   // w-group: w0 + 8wg .. +7
    const int dg = tid >> 4;   // d-group: 8dg .. +7

    const int lo0 = swc(2 * wg);
    const int lo1 = swc(2 * wg + 1);
    // R words rv[n] = word (8wg-8dg+56)+n, n in [0,15]; base 4-aligned.
    const int q0  = 2 * (wg - dg) + 14;          // in [0,44]
    const int ro0 = swc(q0 + 0), ro1 = swc(q0 + 1);
    const int ro2 = swc(q0 + 2), ro3 = swc(q0 + 3);

    float acc[8][8];
    #pragma unroll
    for (int i = 0; i < 8; i++)
        #pragma unroll
        for (int j = 0; j < 8; j++)
            acc[i][j] = 0.0f;

    prefetch(0, 0);
    prefetch(1, 1);

    for (int cc = 0; cc < NCH; cc++) {
        const int st = cc & 1;
        if (cc < NCH - 1) asm volatile("cp.async.wait_group 1;");
        else              asm volatile("cp.async.wait_group 0;");
        __syncthreads();

        const float4* Lp = Ls4 + st * LST;
        const float4* Rp = Rs4 + st * RST;

        #pragma unroll
        for (int c = 0; c < CH; c++) {
            float4 la = Lp[c * LCH + lo0];
            float4 lb = Lp[c * LCH + lo1];
            float4 r0 = Rp[c * RCH + ro0];
            float4 r1 = Rp[c * RCH + ro1];
            float4 r2 = Rp[c * RCH + ro2];
            float4 r3 = Rp[c * RCH + ro3];

            float l[8]   = { la.x, la.y, la.z, la.w, lb.x, lb.y, lb.z, lb.w };
            float rv[16] = { r0.x, r0.y, r0.z, r0.w,  r1.x, r1.y, r1.z, r1.w,
                             r2.x, r2.y, r2.z, r2.w,  r3.x, r3.y, r3.z, r3.w };

            #pragma unroll
            for (int i = 0; i < 8; i++)
                #pragma unroll
                for (int j = 0; j < 8; j++)
                    acc[i][j] += l[i] * rv[8 + i - j];   // n in [1,15]
        }

        __syncthreads();
        if (cc + 2 < NCH) prefetch(cc + 2, st);
    }

    // ---- Epilogue: scale by 1/C, streaming vectorized stores ----
    const float sc = 1.0f / (float)Cn;
    float* ob = out + ((long)(b * Dn) * Hn + h) * Wn + w0 + wg * 8;
    #pragma unroll
    for (int j = 0; j < 8; j++) {
        int d = dg * 8 + j;
        float4 v0 = make_float4(acc[0][j] * sc, acc[1][j] * sc,
                                acc[2][j] * sc, acc[3][j] * sc);
        float4 v1 = make_float4(acc[4][j] * sc, acc[5][j] * sc,
                                acc[6][j] * sc, acc[7][j] * sc);
        float4* p = reinterpret_cast<float4*>(ob + (long)d * Hn * Wn);
        __stcs(p + 0, v0);
        __stcs(p + 1, v1);
    }
}

extern "C" void kernel_launch(void* const* d_in, const int* in_sizes, int n_in,
                              void* d_out, int out_size)
{
    const float* left  = (const float*)d_in[0];
    const float* right = (const float*)d_in[1];
    float* out = (float*)d_out;

    dim3 grid(Wn / TW, Hn, Bn);   // (4, 256, 4) = 4096 CTAs
    cost_volume_kernel<<<grid, NT>>>(left, right, out);
}